// round 5
// baseline (speedup 1.0000x reference)
#include <cuda_runtime.h>
#include <math.h>

// ---------------- problem constants ----------------
static constexpr int LAYERS = 32, HEADS = 8, SEQ = 1024, DIM = 128;
static constexpr int VOCAB = 128000, BEAM = 3, HIST = 16;

static constexpr long long KV_IN_ELEMS  = (long long)LAYERS * HEADS * SEQ * DIM;      // 33,554,432
static constexpr long long KV_OUT_ELEMS = KV_IN_ELEMS * BEAM;                          // 100,663,296

// output layout (flattened reference tuple, all as float32)
static constexpr long long OFF_KV      = 0;
static constexpr long long OFF_TOPIDX  = KV_OUT_ELEMS;
static constexpr long long OFF_SAVEID  = OFF_TOPIDX + BEAM;
static constexpr long long OFF_REPPEN  = OFF_SAVEID + (long long)BEAM * (HIST + 1);
static constexpr long long OFF_TOPPROB = OFF_REPPEN + (long long)BEAM * VOCAB;
static constexpr long long OFF_MAXIDX  = OFF_TOPPROB + BEAM;

// ---------------- grids ----------------
static constexpr int NB1       = 64;                                   // topk blocks
static constexpr int KV_BLOCKS = 16384;                                // 2 float4 / thread (R2 geometry)
static constexpr int RP_BLOCKS = (BEAM * VOCAB + 255) / 256;           // 1500

// ---------------- scratch ----------------
__device__ float g_m[NB1];
__device__ float g_s[NB1];
__device__ float g_tv[NB1 * 3];
__device__ int   g_ti[NB1 * 3];
__device__ int   g_topidx[BEAM];
__device__ float g_pen;
__device__ int   g_cnt = 0;      // topk ticket
__device__ int   g_flag = 0;     // topk-done release flag
__device__ int   g_rp_done = 0;  // rp completion counter

// ---------------- helpers ----------------
__device__ __forceinline__ void ins3(float v, int i, float tv[3], int ti[3]) {
    if (v > tv[0] || (v == tv[0] && i < ti[0])) {
        tv[2] = tv[1]; ti[2] = ti[1];
        tv[1] = tv[0]; ti[1] = ti[0];
        tv[0] = v;     ti[0] = i;
    } else if (v > tv[1] || (v == tv[1] && i < ti[1])) {
        tv[2] = tv[1]; ti[2] = ti[1];
        tv[1] = v;     ti[1] = i;
    } else if (v > tv[2] || (v == tv[2] && i < ti[2])) {
        tv[2] = v;     ti[2] = i;
    }
}

__device__ __forceinline__ void merge_state(float& m, float& s, float tv[3], int ti[3],
                                            float om, float os,
                                            float ov0, float ov1, float ov2,
                                            int oi0, int oi1, int oi2) {
    float mm = fmaxf(m, om);
    s = s * __expf(m - mm) + os * __expf(om - mm);
    m = mm;
    ins3(ov0, oi0, tv, ti);
    ins3(ov1, oi1, tv, ti);
    ins3(ov2, oi2, tv, ti);
}

#define WARP_MERGE(MASK, LIMIT, OFF)                                           \
    {                                                                          \
        float om  = __shfl_down_sync(MASK, m, OFF);                            \
        float os  = __shfl_down_sync(MASK, s, OFF);                            \
        float ov0 = __shfl_down_sync(MASK, tv[0], OFF);                        \
        float ov1 = __shfl_down_sync(MASK, tv[1], OFF);                        \
        float ov2 = __shfl_down_sync(MASK, tv[2], OFF);                        \
        int   oi0 = __shfl_down_sync(MASK, ti[0], OFF);                        \
        int   oi1 = __shfl_down_sync(MASK, ti[1], OFF);                        \
        int   oi2 = __shfl_down_sync(MASK, ti[2], OFF);                        \
        if (lane + OFF < LIMIT)                                                \
            merge_state(m, s, tv, ti, om, os, ov0, ov1, ov2, oi0, oi1, oi2);   \
    }

// ---------------- topk kernel (parallel graph branch) ----------------
__global__ void __launch_bounds__(256) topk_kernel(const float* __restrict__ logits,
                                                   const int* __restrict__ save_id,
                                                   const float* __restrict__ penval,
                                                   float* __restrict__ out) {
    const int tid  = threadIdx.x;
    const int gtid = blockIdx.x * 256 + tid;
    const int lane = tid & 31;
    const int wid  = tid >> 5;

    // 4 independent online-softmax accumulators (break serial MUFU chain)
    float m0 = -INFINITY, s0 = 0.f, m1 = -INFINITY, s1 = 0.f;
    float m2 = -INFINITY, s2 = 0.f, m3 = -INFINITY, s3 = 0.f;
    // 2 top-3 sets (break ALU compare chain)
    float tva[3] = {-INFINITY, -INFINITY, -INFINITY};
    int   tia[3] = {VOCAB, VOCAB, VOCAB};
    float tvb[3] = {-INFINITY, -INFINITY, -INFINITY};
    int   tib[3] = {VOCAB, VOCAB, VOCAB};

    const float4* L4 = reinterpret_cast<const float4*>(logits);
    const int NV4 = VOCAB / 4;
    for (int j = gtid; j < NV4; j += NB1 * 256) {
        float4 x = L4[j];
        int i0 = 4 * j;
        if (x.x > m0) { s0 = s0 * __expf(m0 - x.x) + 1.f; m0 = x.x; } else { s0 += __expf(x.x - m0); }
        if (x.y > m1) { s1 = s1 * __expf(m1 - x.y) + 1.f; m1 = x.y; } else { s1 += __expf(x.y - m1); }
        if (x.z > m2) { s2 = s2 * __expf(m2 - x.z) + 1.f; m2 = x.z; } else { s2 += __expf(x.z - m2); }
        if (x.w > m3) { s3 = s3 * __expf(m3 - x.w) + 1.f; m3 = x.w; } else { s3 += __expf(x.w - m3); }
        ins3(x.x, i0 + 0, tva, tia);
        ins3(x.z, i0 + 2, tvb, tib);
        ins3(x.y, i0 + 1, tva, tia);
        ins3(x.w, i0 + 3, tvb, tib);
    }

    // combine 4 (m,s) accumulators
    float m = fmaxf(fmaxf(m0, m1), fmaxf(m2, m3));
    float s = s0 * __expf(m0 - m) + s1 * __expf(m1 - m)
            + s2 * __expf(m2 - m) + s3 * __expf(m3 - m);
    // combine top-3 sets
    float tv[3] = {tva[0], tva[1], tva[2]};
    int   ti[3] = {tia[0], tia[1], tia[2]};
    ins3(tvb[0], tib[0], tv, ti);
    ins3(tvb[1], tib[1], tv, ti);
    ins3(tvb[2], tib[2], tv, ti);

    WARP_MERGE(0xffffffffu, 32, 16)
    WARP_MERGE(0xffffffffu, 32, 8)
    WARP_MERGE(0xffffffffu, 32, 4)
    WARP_MERGE(0xffffffffu, 32, 2)
    WARP_MERGE(0xffffffffu, 32, 1)

    __shared__ float sm[8], ss[8], stv[8][3];
    __shared__ int   sti[8][3];
    if (lane == 0) {
        sm[wid] = m; ss[wid] = s;
        stv[wid][0] = tv[0]; stv[wid][1] = tv[1]; stv[wid][2] = tv[2];
        sti[wid][0] = ti[0]; sti[wid][1] = ti[1]; sti[wid][2] = ti[2];
    }
    __syncthreads();

    if (wid == 0 && lane < 8) {
        m = sm[lane]; s = ss[lane];
        tv[0] = stv[lane][0]; tv[1] = stv[lane][1]; tv[2] = stv[lane][2];
        ti[0] = sti[lane][0]; ti[1] = sti[lane][1]; ti[2] = sti[lane][2];
        WARP_MERGE(0x000000ffu, 8, 4)
        WARP_MERGE(0x000000ffu, 8, 2)
        WARP_MERGE(0x000000ffu, 8, 1)
        if (lane == 0) {
            g_m[blockIdx.x] = m;
            g_s[blockIdx.x] = s;
            g_tv[blockIdx.x * 3 + 0] = tv[0]; g_ti[blockIdx.x * 3 + 0] = ti[0];
            g_tv[blockIdx.x * 3 + 1] = tv[1]; g_ti[blockIdx.x * 3 + 1] = ti[1];
            g_tv[blockIdx.x * 3 + 2] = tv[2]; g_ti[blockIdx.x * 3 + 2] = ti[2];
        }
    }

    // last-block ticket
    __shared__ bool amLast;
    __threadfence();
    if (tid == 0) {
        int prev = atomicAdd(&g_cnt, 1);
        amLast = (prev == NB1 - 1);
        if (amLast) g_cnt = 0;
    }
    __syncthreads();
    if (!amLast) return;

    // final merge of 64 partials
    __shared__ float fin_m, fin_s, fin_tv[3];
    __shared__ int   fin_ti[3];
    if (tid < 32) {
        float mm2 = g_m[tid], ss2 = g_s[tid];
        float tv2[3] = {g_tv[tid * 3 + 0], g_tv[tid * 3 + 1], g_tv[tid * 3 + 2]};
        int   ti2[3] = {g_ti[tid * 3 + 0], g_ti[tid * 3 + 1], g_ti[tid * 3 + 2]};
        {
            int j = tid + 32;
            merge_state(mm2, ss2, tv2, ti2, g_m[j], g_s[j],
                        g_tv[j * 3 + 0], g_tv[j * 3 + 1], g_tv[j * 3 + 2],
                        g_ti[j * 3 + 0], g_ti[j * 3 + 1], g_ti[j * 3 + 2]);
        }
        float m = mm2, s = ss2;
        float tv[3] = {tv2[0], tv2[1], tv2[2]};
        int   ti[3] = {ti2[0], ti2[1], ti2[2]};
        int lane = tid;
        WARP_MERGE(0xffffffffu, 32, 16)
        WARP_MERGE(0xffffffffu, 32, 8)
        WARP_MERGE(0xffffffffu, 32, 4)
        WARP_MERGE(0xffffffffu, 32, 2)
        WARP_MERGE(0xffffffffu, 32, 1)
        if (tid == 0) {
            fin_m = m; fin_s = s;
            fin_tv[0] = tv[0]; fin_tv[1] = tv[1]; fin_tv[2] = tv[2];
            fin_ti[0] = ti[0]; fin_ti[1] = ti[1]; fin_ti[2] = ti[2];
        }
    }
    __syncthreads();

    const float logZ = fin_m + logf(fin_s);

    if (tid < BEAM) {
        out[OFF_TOPIDX  + tid] = (float)fin_ti[tid];
        out[OFF_TOPPROB + tid] = fin_tv[tid] - logZ;
        g_topidx[tid] = fin_ti[tid];
    }
    if (tid == 0) g_pen = penval[0];
    if (tid == 0) out[OFF_MAXIDX] = (float)fin_ti[0];
    if (tid < BEAM * (HIST + 1)) {
        int r = tid / (HIST + 1);
        int c = tid % (HIST + 1);
        out[OFF_SAVEID + tid] = (c < HIST) ? (float)save_id[r * HIST + c]
                                           : (float)fin_ti[r];
    }

    // publish
    __threadfence();
    __syncthreads();
    if (tid == 0) *((volatile int*)&g_flag) = 1;
}

// ---------------- kv + rp kernel (R2 hot path, parallel graph branch) ----------------
__global__ void __launch_bounds__(256) kv_rp_kernel(const float4* __restrict__ in,
                                                    const float* __restrict__ rp,
                                                    float* __restrict__ outf) {
    const int tid = threadIdx.x;

    if (blockIdx.x < KV_BLOCKS) {
        // KV replicate: 2 independent float4 per thread
        const unsigned INNER = (unsigned)(HEADS * SEQ * DIM) / 4;   // 262144 (2^18)
        float4* out = reinterpret_cast<float4*>(outf + OFF_KV);
        unsigned base = blockIdx.x * 512u + (unsigned)tid;          // layer-aligned 512-f4 chunk
        unsigned i0 = base, i1 = base + 256u;

        float4 v0 = __ldcs(in + i0);
        float4 v1 = __ldcs(in + i1);

        unsigned l  = i0 >> 18;
        unsigned r0 = i0 & (INNER - 1);
        unsigned r1 = i1 & (INNER - 1);
        float4* o = out + (unsigned long long)l * 3u * INNER;
        __stcs(o + r0,              v0);
        __stcs(o + r1,              v1);
        __stcs(o + INNER + r0,      v0);
        __stcs(o + INNER + r1,      v1);
        __stcs(o + 2u * INNER + r0, v0);
        __stcs(o + 2u * INNER + r1, v1);
        return;
    }

    // repeat-penalty: unconditional copy (independent of topk)
    int i = (blockIdx.x - KV_BLOCKS) * 256 + tid;
    if (i < BEAM * VOCAB) {
        outf[OFF_REPPEN + i] = rp[i];
    }

    // last rp block patches the 3 penalized elements (waits on topk branch)
    __threadfence();
    __syncthreads();
    if (tid == 0) {
        int prev = atomicAdd(&g_rp_done, 1);
        if (prev == RP_BLOCKS - 1) {
            g_rp_done = 0;
            while (*((volatile int*)&g_flag) == 0) { __nanosleep(64); }
            __threadfence();
            float pen = *((volatile float*)&g_pen);
#pragma unroll
            for (int r = 0; r < BEAM; r++) {
                int t = *((volatile int*)&g_topidx[r]);
                outf[OFF_REPPEN + (long long)r * VOCAB + t] = rp[(long long)r * VOCAB + t] * pen;
            }
            __threadfence();
            g_flag = 0;   // reset for replay determinism
        }
    }
}

// ---------------- launch: fork/join for parallel graph branches ----------------
extern "C" void kernel_launch(void* const* d_in, const int* in_sizes, int n_in,
                              void* d_out, int out_size) {
    const float* kv      = (const float*)d_in[0];
    const float* logits  = (const float*)d_in[1];
    const int*   save_id = (const int*)d_in[2];
    const float* reppen  = (const float*)d_in[3];
    const float* penval  = (const float*)d_in[4];
    float* out = (float*)d_out;

    cudaStream_t s2;
    cudaEvent_t  eFork, eJoin;
    cudaStreamCreateWithFlags(&s2, cudaStreamNonBlocking);
    cudaEventCreateWithFlags(&eFork, cudaEventDisableTiming);
    cudaEventCreateWithFlags(&eJoin, cudaEventDisableTiming);

    // fork: s2 branches off the capture stream
    cudaEventRecord(eFork, 0);
    cudaStreamWaitEvent(s2, eFork, 0);

    // branch A (side stream): topk — small, hides under the copy
    topk_kernel<<<NB1, 256, 0, s2>>>(logits, save_id, penval, out);

    // branch B (main capture stream): DRAM-bound KV replicate + rp copy/fixup
    kv_rp_kernel<<<KV_BLOCKS + RP_BLOCKS, 256>>>((const float4*)kv, reppen, out);

    // join: main stream waits for topk branch
    cudaEventRecord(eJoin, s2);
    cudaStreamWaitEvent(0, eJoin, 0);
    // (stream/event objects intentionally not destroyed mid-capture; host-side only)
}

// round 6
// speedup vs baseline: 1.0422x; 1.0422x over previous
#include <cuda_runtime.h>
#include <math.h>

// ---------------- problem constants ----------------
static constexpr int LAYERS = 32, HEADS = 8, SEQ = 1024, DIM = 128;
static constexpr int VOCAB = 128000, BEAM = 3, HIST = 16;

static constexpr long long KV_IN_ELEMS  = (long long)LAYERS * HEADS * SEQ * DIM;      // 33,554,432
static constexpr long long KV_OUT_ELEMS = KV_IN_ELEMS * BEAM;                          // 100,663,296

// output layout (flattened reference tuple, all as float32)
static constexpr long long OFF_KV      = 0;
static constexpr long long OFF_TOPIDX  = KV_OUT_ELEMS;
static constexpr long long OFF_SAVEID  = OFF_TOPIDX + BEAM;
static constexpr long long OFF_REPPEN  = OFF_SAVEID + (long long)BEAM * (HIST + 1);
static constexpr long long OFF_TOPPROB = OFF_REPPEN + (long long)BEAM * VOCAB;
static constexpr long long OFF_MAXIDX  = OFF_TOPPROB + BEAM;

// ---------------- grid layout (single kernel) ----------------
static constexpr int NB1       = 64;                                   // topk blocks
static constexpr int KV_BLOCKS = 8192;                                 // 4 float4 / thread (R3 fused-best)
static constexpr int RP_BLOCKS = (BEAM * VOCAB + 255) / 256;           // 1500
static constexpr int KV_END    = NB1 + KV_BLOCKS;
static constexpr int GRID      = KV_END + RP_BLOCKS;

// ---------------- scratch ----------------
__device__ float g_m[NB1];
__device__ float g_s[NB1];
__device__ float g_tv[NB1 * 3];
__device__ int   g_ti[NB1 * 3];
__device__ int   g_topidx[BEAM];
__device__ float g_pen;
__device__ int   g_cnt = 0;      // topk ticket
__device__ int   g_flag = 0;     // topk-done release flag
__device__ int   g_rp_done = 0;  // rp completion counter

// ---------------- helpers ----------------
__device__ __forceinline__ void ins3(float v, int i, float tv[3], int ti[3]) {
    if (v > tv[0] || (v == tv[0] && i < ti[0])) {
        tv[2] = tv[1]; ti[2] = ti[1];
        tv[1] = tv[0]; ti[1] = ti[0];
        tv[0] = v;     ti[0] = i;
    } else if (v > tv[1] || (v == tv[1] && i < ti[1])) {
        tv[2] = tv[1]; ti[2] = ti[1];
        tv[1] = v;     ti[1] = i;
    } else if (v > tv[2] || (v == tv[2] && i < ti[2])) {
        tv[2] = v;     ti[2] = i;
    }
}

__device__ __forceinline__ void merge_state(float& m, float& s, float tv[3], int ti[3],
                                            float om, float os,
                                            float ov0, float ov1, float ov2,
                                            int oi0, int oi1, int oi2) {
    float mm = fmaxf(m, om);
    s = s * __expf(m - mm) + os * __expf(om - mm);
    m = mm;
    ins3(ov0, oi0, tv, ti);
    ins3(ov1, oi1, tv, ti);
    ins3(ov2, oi2, tv, ti);
}

#define WARP_MERGE(MASK, LIMIT, OFF)                                           \
    {                                                                          \
        float om  = __shfl_down_sync(MASK, m, OFF);                            \
        float os  = __shfl_down_sync(MASK, s, OFF);                            \
        float ov0 = __shfl_down_sync(MASK, tv[0], OFF);                        \
        float ov1 = __shfl_down_sync(MASK, tv[1], OFF);                        \
        float ov2 = __shfl_down_sync(MASK, tv[2], OFF);                        \
        int   oi0 = __shfl_down_sync(MASK, ti[0], OFF);                        \
        int   oi1 = __shfl_down_sync(MASK, ti[1], OFF);                        \
        int   oi2 = __shfl_down_sync(MASK, ti[2], OFF);                        \
        if (lane + OFF < LIMIT)                                                \
            merge_state(m, s, tv, ti, om, os, ov0, ov1, ov2, oi0, oi1, oi2);   \
    }

// ---------------- topk role (blocks 0..63) — fast 4-way-split version ----------------
__device__ void topk_role(int bid,
                          const float* __restrict__ logits,
                          const int* __restrict__ save_id,
                          const float* __restrict__ penval,
                          float* __restrict__ out) {
    const int tid  = threadIdx.x;
    const int gtid = bid * 256 + tid;
    const int lane = tid & 31;
    const int wid  = tid >> 5;

    // 4 independent online-softmax accumulators (break serial MUFU chain)
    float m0 = -INFINITY, s0 = 0.f, m1 = -INFINITY, s1 = 0.f;
    float m2 = -INFINITY, s2 = 0.f, m3 = -INFINITY, s3 = 0.f;
    // 2 top-3 sets (break ALU compare chain)
    float tva[3] = {-INFINITY, -INFINITY, -INFINITY};
    int   tia[3] = {VOCAB, VOCAB, VOCAB};
    float tvb[3] = {-INFINITY, -INFINITY, -INFINITY};
    int   tib[3] = {VOCAB, VOCAB, VOCAB};

    const float4* L4 = reinterpret_cast<const float4*>(logits);
    const int NV4 = VOCAB / 4;
    for (int j = gtid; j < NV4; j += NB1 * 256) {
        float4 x = L4[j];
        int i0 = 4 * j;
        if (x.x > m0) { s0 = s0 * __expf(m0 - x.x) + 1.f; m0 = x.x; } else { s0 += __expf(x.x - m0); }
        if (x.y > m1) { s1 = s1 * __expf(m1 - x.y) + 1.f; m1 = x.y; } else { s1 += __expf(x.y - m1); }
        if (x.z > m2) { s2 = s2 * __expf(m2 - x.z) + 1.f; m2 = x.z; } else { s2 += __expf(x.z - m2); }
        if (x.w > m3) { s3 = s3 * __expf(m3 - x.w) + 1.f; m3 = x.w; } else { s3 += __expf(x.w - m3); }
        ins3(x.x, i0 + 0, tva, tia);
        ins3(x.z, i0 + 2, tvb, tib);
        ins3(x.y, i0 + 1, tva, tia);
        ins3(x.w, i0 + 3, tvb, tib);
    }

    // combine accumulators / top-3 sets
    float m = fmaxf(fmaxf(m0, m1), fmaxf(m2, m3));
    float s = s0 * __expf(m0 - m) + s1 * __expf(m1 - m)
            + s2 * __expf(m2 - m) + s3 * __expf(m3 - m);
    float tv[3] = {tva[0], tva[1], tva[2]};
    int   ti[3] = {tia[0], tia[1], tia[2]};
    ins3(tvb[0], tib[0], tv, ti);
    ins3(tvb[1], tib[1], tv, ti);
    ins3(tvb[2], tib[2], tv, ti);

    WARP_MERGE(0xffffffffu, 32, 16)
    WARP_MERGE(0xffffffffu, 32, 8)
    WARP_MERGE(0xffffffffu, 32, 4)
    WARP_MERGE(0xffffffffu, 32, 2)
    WARP_MERGE(0xffffffffu, 32, 1)

    __shared__ float sm[8], ss[8], stv[8][3];
    __shared__ int   sti[8][3];
    if (lane == 0) {
        sm[wid] = m; ss[wid] = s;
        stv[wid][0] = tv[0]; stv[wid][1] = tv[1]; stv[wid][2] = tv[2];
        sti[wid][0] = ti[0]; sti[wid][1] = ti[1]; sti[wid][2] = ti[2];
    }
    __syncthreads();

    if (wid == 0 && lane < 8) {
        m = sm[lane]; s = ss[lane];
        tv[0] = stv[lane][0]; tv[1] = stv[lane][1]; tv[2] = stv[lane][2];
        ti[0] = sti[lane][0]; ti[1] = sti[lane][1]; ti[2] = sti[lane][2];
        WARP_MERGE(0x000000ffu, 8, 4)
        WARP_MERGE(0x000000ffu, 8, 2)
        WARP_MERGE(0x000000ffu, 8, 1)
        if (lane == 0) {
            g_m[bid] = m;
            g_s[bid] = s;
            g_tv[bid * 3 + 0] = tv[0]; g_ti[bid * 3 + 0] = ti[0];
            g_tv[bid * 3 + 1] = tv[1]; g_ti[bid * 3 + 1] = ti[1];
            g_tv[bid * 3 + 2] = tv[2]; g_ti[bid * 3 + 2] = ti[2];
        }
    }

    // last-block ticket
    __shared__ bool amLast;
    __threadfence();
    if (tid == 0) {
        int prev = atomicAdd(&g_cnt, 1);
        amLast = (prev == NB1 - 1);
        if (amLast) g_cnt = 0;
    }
    __syncthreads();
    if (!amLast) return;

    // final merge of 64 partials
    __shared__ float fin_m, fin_s, fin_tv[3];
    __shared__ int   fin_ti[3];
    if (tid < 32) {
        float mm2 = g_m[tid], ss2 = g_s[tid];
        float tv2[3] = {g_tv[tid * 3 + 0], g_tv[tid * 3 + 1], g_tv[tid * 3 + 2]};
        int   ti2[3] = {g_ti[tid * 3 + 0], g_ti[tid * 3 + 1], g_ti[tid * 3 + 2]};
        {
            int j = tid + 32;
            merge_state(mm2, ss2, tv2, ti2, g_m[j], g_s[j],
                        g_tv[j * 3 + 0], g_tv[j * 3 + 1], g_tv[j * 3 + 2],
                        g_ti[j * 3 + 0], g_ti[j * 3 + 1], g_ti[j * 3 + 2]);
        }
        float m = mm2, s = ss2;
        float tv[3] = {tv2[0], tv2[1], tv2[2]};
        int   ti[3] = {ti2[0], ti2[1], ti2[2]};
        int lane = tid;
        WARP_MERGE(0xffffffffu, 32, 16)
        WARP_MERGE(0xffffffffu, 32, 8)
        WARP_MERGE(0xffffffffu, 32, 4)
        WARP_MERGE(0xffffffffu, 32, 2)
        WARP_MERGE(0xffffffffu, 32, 1)
        if (tid == 0) {
            fin_m = m; fin_s = s;
            fin_tv[0] = tv[0]; fin_tv[1] = tv[1]; fin_tv[2] = tv[2];
            fin_ti[0] = ti[0]; fin_ti[1] = ti[1]; fin_ti[2] = ti[2];
        }
    }
    __syncthreads();

    const float logZ = fin_m + logf(fin_s);

    if (tid < BEAM) {
        out[OFF_TOPIDX  + tid] = (float)fin_ti[tid];
        out[OFF_TOPPROB + tid] = fin_tv[tid] - logZ;
        g_topidx[tid] = fin_ti[tid];
    }
    if (tid == 0) g_pen = penval[0];
    if (tid == 0) out[OFF_MAXIDX] = (float)fin_ti[0];
    if (tid < BEAM * (HIST + 1)) {
        int r = tid / (HIST + 1);
        int c = tid % (HIST + 1);
        out[OFF_SAVEID + tid] = (c < HIST) ? (float)save_id[r * HIST + c]
                                           : (float)fin_ti[r];
    }

    // publish
    __threadfence();
    __syncthreads();
    if (tid == 0) *((volatile int*)&g_flag) = 1;
}

// ---------------- single fused kernel ----------------
__global__ void __launch_bounds__(256) fused_kernel(const float4* __restrict__ kv,
                                                    const float* __restrict__ logits,
                                                    const int* __restrict__ save_id,
                                                    const float* __restrict__ rp,
                                                    const float* __restrict__ penval,
                                                    float* __restrict__ outf) {
    const int bid = blockIdx.x;
    const int tid = threadIdx.x;

    if (bid < NB1) {
        topk_role(bid, logits, save_id, penval, outf);
        return;
    }

    if (bid < KV_END) {
        // ---- KV replicate: 4 independent float4 per thread (MLP=4) ----
        const unsigned INNER = (unsigned)(HEADS * SEQ * DIM) / 4;   // 262144 (2^18)
        float4* out = reinterpret_cast<float4*>(outf + OFF_KV);
        unsigned base = (unsigned)(bid - NB1) * 1024u + (unsigned)tid;  // 1024 f4/block, layer-aligned

        float4 v0 = __ldcs(kv + base);
        float4 v1 = __ldcs(kv + base + 256u);
        float4 v2 = __ldcs(kv + base + 512u);
        float4 v3 = __ldcs(kv + base + 768u);

        unsigned l = base >> 18;                 // all 4 in same layer (1024 | 262144)
        unsigned r = base & (INNER - 1);
        float4* o = out + (unsigned long long)l * 3u * INNER + r;
#pragma unroll
        for (int b = 0; b < 3; b++) {
            __stcs(o,        v0);
            __stcs(o + 256,  v1);
            __stcs(o + 512,  v2);
            __stcs(o + 768,  v3);
            o += INNER;
        }
        return;
    }

    // ---- repeat-penalty role: unconditional copy (no dependency on topk) ----
    int i = (bid - KV_END) * 256 + tid;
    if (i < BEAM * VOCAB) {
        outf[OFF_REPPEN + i] = rp[i];
    }

    // last rp block patches the 3 penalized elements
    __threadfence();
    __syncthreads();
    if (tid == 0) {
        int prev = atomicAdd(&g_rp_done, 1);
        if (prev == RP_BLOCKS - 1) {
            g_rp_done = 0;
            while (*((volatile int*)&g_flag) == 0) { __nanosleep(64); }
            __threadfence();
            float pen = *((volatile float*)&g_pen);
#pragma unroll
            for (int r = 0; r < BEAM; r++) {
                int t = *((volatile int*)&g_topidx[r]);
                outf[OFF_REPPEN + (long long)r * VOCAB + t] = rp[(long long)r * VOCAB + t] * pen;
            }
            __threadfence();
            g_flag = 0;   // reset for replay determinism
        }
    }
}

// ---------------- launch ----------------
extern "C" void kernel_launch(void* const* d_in, const int* in_sizes, int n_in,
                              void* d_out, int out_size) {
    const float* kv      = (const float*)d_in[0];
    const float* logits  = (const float*)d_in[1];
    const int*   save_id = (const int*)d_in[2];
    const float* reppen  = (const float*)d_in[3];
    const float* penval  = (const float*)d_in[4];
    float* out = (float*)d_out;

    fused_kernel<<<GRID, 256>>>((const float4*)kv, logits, save_id, reppen, penval, out);
}